// round 6
// baseline (speedup 1.0000x reference)
#include <cuda_runtime.h>
#include <stdint.h>
#include <math.h>

#define B_ 8192
#define D_ 2048
#define C_ 4096
#define K_ 1000
#define KPAD_ 1024

// smem geometry: rows of 64B data + 16B pad (ldmatrix conflict-free: 5r+g mod 8)
#define ROWB8 80
#define PART8 (128 * ROWB8)      // 10240
#define BUF8  (4 * PART8)        // 40960
#define SMEM8 (2 * BUF8)         // 81920

// ---------------------------------------------------------------------------
// Device scratch
// ---------------------------------------------------------------------------
__device__ __align__(128) int8_t g_xq1[(size_t)B_ * D_], g_xq2[(size_t)B_ * D_];
__device__ __align__(128) int8_t g_cq1[(size_t)C_ * D_], g_cq2[(size_t)C_ * D_];
__device__ __align__(128) int8_t g_wq1[(size_t)KPAD_ * C_], g_wq2[(size_t)KPAD_ * C_];
__device__ __align__(128) int8_t g_aq1[(size_t)B_ * C_], g_aq2[(size_t)B_ * C_];
__device__ __align__(128) float  g_t[(size_t)B_ * C_];
__device__ float g_ux[B_], g_vc[C_], g_wk[KPAD_];
__device__ float g_x2[B_], g_c2[C_], g_rowsum[B_];
__device__ int   g_tmin[B_];     // float bits, atomicMin (t >= 0)

// ---------------------------------------------------------------------------
// PTX helpers
// ---------------------------------------------------------------------------
__device__ __forceinline__ uint32_t smem_u32(const void* p) {
    uint32_t a;
    asm("{ .reg .u64 t; cvta.to.shared.u64 t, %1; cvt.u32.u64 %0, t; }"
        : "=r"(a) : "l"(p));
    return a;
}

__device__ __forceinline__ void ldsm_x4(uint32_t& r0, uint32_t& r1, uint32_t& r2,
                                        uint32_t& r3, uint32_t addr) {
    asm volatile("ldmatrix.sync.aligned.m8n8.x4.shared.b16 {%0,%1,%2,%3}, [%4];"
                 : "=r"(r0), "=r"(r1), "=r"(r2), "=r"(r3) : "r"(addr));
}

__device__ __forceinline__ void mma_s8(int c[4], const uint32_t a[4],
                                       const uint32_t b[2]) {
    asm volatile(
        "mma.sync.aligned.m16n8k32.row.col.s32.s8.s8.s32 "
        "{%0,%1,%2,%3}, {%4,%5,%6,%7}, {%8,%9}, {%0,%1,%2,%3};"
        : "+r"(c[0]), "+r"(c[1]), "+r"(c[2]), "+r"(c[3])
        : "r"(a[0]), "r"(a[1]), "r"(a[2]), "r"(a[3]), "r"(b[0]), "r"(b[1]));
}

__device__ __forceinline__ void cp16(uint32_t dst, const void* src) {
    asm volatile("cp.async.cg.shared.global [%0], [%1], 16;"
                 :: "r"(dst), "l"(src) : "memory");
}
#define CP_COMMIT() asm volatile("cp.async.commit_group;" ::: "memory")
template <int N>
__device__ __forceinline__ void cp_wait() {
    asm volatile("cp.async.wait_group %0;" :: "n"(N) : "memory");
}

__device__ __forceinline__ uint32_t pack4(int a, int b, int c, int d) {
    return (uint32_t)(uint8_t)(int8_t)a | ((uint32_t)(uint8_t)(int8_t)b << 8) |
           ((uint32_t)(uint8_t)(int8_t)c << 16) | ((uint32_t)(uint8_t)(int8_t)d << 24);
}

// ---------------------------------------------------------------------------
// Quantize input rows: per-row scale u = max|row|/127, two s8 digits (radix 254).
// WHICH: 0 = x (also x2, tmin init), 1 = centers (c2), 2 = W (zero-pad rows >= K_).
// ---------------------------------------------------------------------------
template <int DIM, int WHICH>
__global__ void quant_kernel(const float* __restrict__ src,
                             int8_t* __restrict__ q1, int8_t* __restrict__ q2) {
    __shared__ float buf[DIM];
    __shared__ float redmx[8], redss[8];
    const int row = blockIdx.x;
    const int tid = threadIdx.x;
    const bool valid = (WHICH != 2) || (row < K_);
    const float* p = src + (size_t)row * DIM;

    float mx = 0.f, ss = 0.f;
    for (int i = tid * 4; i < DIM; i += 1024) {
        float4 v = valid ? *reinterpret_cast<const float4*>(p + i)
                         : make_float4(0.f, 0.f, 0.f, 0.f);
        buf[i] = v.x; buf[i + 1] = v.y; buf[i + 2] = v.z; buf[i + 3] = v.w;
        mx = fmaxf(mx, fmaxf(fmaxf(fabsf(v.x), fabsf(v.y)),
                             fmaxf(fabsf(v.z), fabsf(v.w))));
        ss += v.x * v.x + v.y * v.y + v.z * v.z + v.w * v.w;
    }
    #pragma unroll
    for (int o = 16; o; o >>= 1) {
        mx = fmaxf(mx, __shfl_xor_sync(0xffffffffu, mx, o));
        ss += __shfl_xor_sync(0xffffffffu, ss, o);
    }
    if ((tid & 31) == 0) { redmx[tid >> 5] = mx; redss[tid >> 5] = ss; }
    __syncthreads();
    float fmx = 0.f, fss = 0.f;
    #pragma unroll
    for (int i = 0; i < 8; i++) { fmx = fmaxf(fmx, redmx[i]); fss += redss[i]; }

    const float u = (fmx > 0.f) ? fmx * (1.f / 127.f) : 1.f;
    const float invu = 1.f / u;

    for (int i = tid * 4; i < DIM; i += 1024) {
        int c1[4], c2[4];
        #pragma unroll
        for (int j = 0; j < 4; j++) {
            float v = buf[i + j];
            float qf = rintf(v * invu);
            float r = v - qf * u;
            float q2f = rintf(r * invu * 254.f);
            q2f = fminf(fmaxf(q2f, -127.f), 127.f);
            c1[j] = (int)qf;
            c2[j] = (int)q2f;
        }
        *reinterpret_cast<uint32_t*>(q1 + (size_t)row * DIM + i) =
            pack4(c1[0], c1[1], c1[2], c1[3]);
        *reinterpret_cast<uint32_t*>(q2 + (size_t)row * DIM + i) =
            pack4(c2[0], c2[1], c2[2], c2[3]);
    }
    if (tid == 0) {
        if (WHICH == 0) { g_ux[row] = u; g_x2[row] = fss; g_tmin[row] = 0x7f800000; }
        else if (WHICH == 1) { g_vc[row] = u; g_c2[row] = fss; }
        else { g_wk[row] = u; }
    }
}

// ---------------------------------------------------------------------------
// act quantization: act' = exp(tmin - t) in (0,1], fixed scale 1/127, 2 digits.
// One block per row; exact block-wide rowsum (no atomics).
// ---------------------------------------------------------------------------
__global__ void actquant_kernel(const float* __restrict__ tarr,
                                int8_t* __restrict__ aq1,
                                int8_t* __restrict__ aq2) {
    const int row = blockIdx.x;
    const int tid = threadIdx.x;
    const float tm = __int_as_float(g_tmin[row]);
    const float* tp = tarr + (size_t)row * C_;
    float s = 0.f;
    #pragma unroll
    for (int j = 0; j < C_ / 1024; j++) {
        const int idx = j * 1024 + tid * 4;
        float4 t4 = *reinterpret_cast<const float4*>(tp + idx);
        float a[4] = {__expf(tm - t4.x), __expf(tm - t4.y),
                      __expf(tm - t4.z), __expf(tm - t4.w)};
        int c1[4], c2[4];
        #pragma unroll
        for (int q = 0; q < 4; q++) {
            s += a[q];
            float qf = rintf(a[q] * 127.f);
            float r = a[q] - qf * (1.f / 127.f);
            float q2f = rintf(r * (127.f * 254.f));
            q2f = fminf(fmaxf(q2f, -127.f), 127.f);
            c1[q] = (int)qf; c2[q] = (int)q2f;
        }
        *reinterpret_cast<uint32_t*>(aq1 + (size_t)row * C_ + idx) =
            pack4(c1[0], c1[1], c1[2], c1[3]);
        *reinterpret_cast<uint32_t*>(aq2 + (size_t)row * C_ + idx) =
            pack4(c2[0], c2[1], c2[2], c2[3]);
    }
    #pragma unroll
    for (int o = 16; o; o >>= 1) s += __shfl_xor_sync(0xffffffffu, s, o);
    __shared__ float ws[8];
    if ((tid & 31) == 0) ws[tid >> 5] = s;
    __syncthreads();
    if (tid == 0) {
        float t = 0.f;
        #pragma unroll
        for (int i = 0; i < 8; i++) t += ws[i];
        g_rowsum[row] = t;
    }
}

// ---------------------------------------------------------------------------
// int8 GEMM: CTA 128x128, 512 threads (16 warps, warp tile 32x32), K-chunk 64,
// cp.async double-buffered. Passes per k32: q1p1->ACC0, q1p2->ACC1, q2p1->ACC1.
// dot = u*v*(ACC0 + ACC1/254).
// MODE 0: t = beta*dist epilogue (writes g_t + row atomicMin).
// MODE 1: out = (1/127)*w*(Q0+Q1/254)/rowsum + bias.
// ---------------------------------------------------------------------------
template <int KDIM, int MODE>
__global__ __launch_bounds__(512, 1) void gemm_s8_kernel(
    const int8_t* __restrict__ Aq1, const int8_t* __restrict__ Aq2,
    const int8_t* __restrict__ Bq1, const int8_t* __restrict__ Bq2,
    const float* __restrict__ beta, const float* __restrict__ bias,
    float* __restrict__ out)
{
    extern __shared__ char smem[];
    const uint32_t sb = smem_u32(smem);
    const int tid = threadIdx.x;
    const int w = tid >> 5, lane = tid & 31;
    const int warp_m = w >> 2, warp_n = w & 3;      // 4x4 warps, 32x32 tiles
    const int bx = blockIdx.x, by = blockIdx.y;

    // ---- loader: 4 parts (Aq1,Aq2,Bq1,Bq2) x 128 threads; 4 x 16B per thread ----
    const int part = tid >> 7;
    const int lrow = tid & 127;
    const int8_t* srcBase =
        (part == 0) ? Aq1 : (part == 1) ? Aq2 : (part == 2) ? Bq1 : Bq2;
    const int rbase = (part < 2) ? by * 128 : bx * 128;
    const int8_t* src0 = srcBase + (size_t)(rbase + lrow) * KDIM;
    const uint32_t dst0 = sb + part * PART8 + lrow * ROWB8;

    int acc0[2][4][4], acc1[2][4][4];
    #pragma unroll
    for (int mt = 0; mt < 2; mt++)
        #pragma unroll
        for (int nt = 0; nt < 4; nt++)
            #pragma unroll
            for (int q = 0; q < 4; q++) { acc0[mt][nt][q] = 0; acc1[mt][nt][q] = 0; }

    constexpr int NCH = KDIM / 64;

    // chunk 0
    #pragma unroll
    for (int g = 0; g < 4; g++)
        cp16(dst0 + g * 16, src0 + g * 16);
    CP_COMMIT();

    // fragment base addresses (80B rows)
    const uint32_t a_base = (uint32_t)(warp_m * 32 + (lane & 7) + ((lane >> 3) & 1) * 8) * ROWB8 +
                            (uint32_t)(lane >> 4) * 16;
    const uint32_t b_base = 2 * PART8 +
                            (uint32_t)(warp_n * 32 + (lane & 7) + ((lane >> 4) << 3)) * ROWB8 +
                            (uint32_t)((lane >> 3) & 1) * 16;

    for (int c = 0; c < NCH; c++) {
        if (c + 1 < NCH) {
            const int8_t* s = src0 + (size_t)(c + 1) * 64;
            const uint32_t d = dst0 + ((c + 1) & 1) * BUF8;
            #pragma unroll
            for (int g = 0; g < 4; g++)
                cp16(d + g * 16, s + g * 16);
            CP_COMMIT();
            cp_wait<1>();
        } else {
            cp_wait<0>();
        }
        __syncthreads();

        const uint32_t bufb = sb + (c & 1) * BUF8;
        #pragma unroll
        for (int ks = 0; ks < 2; ks++) {
            const uint32_t kso = ks * 32;
            uint32_t A1[2][4], A2[2][4], B1[4][2], B2[4][2];
            #pragma unroll
            for (int mt = 0; mt < 2; mt++) {
                ldsm_x4(A1[mt][0], A1[mt][1], A1[mt][2], A1[mt][3],
                        bufb + a_base + mt * (16 * ROWB8) + kso);
                ldsm_x4(A2[mt][0], A2[mt][1], A2[mt][2], A2[mt][3],
                        bufb + PART8 + a_base + mt * (16 * ROWB8) + kso);
            }
            #pragma unroll
            for (int np = 0; np < 2; np++) {
                uint32_t r0, r1, r2, r3;
                ldsm_x4(r0, r1, r2, r3, bufb + b_base + np * (16 * ROWB8) + kso);
                B1[np * 2][0] = r0; B1[np * 2][1] = r1;
                B1[np * 2 + 1][0] = r2; B1[np * 2 + 1][1] = r3;
                ldsm_x4(r0, r1, r2, r3, bufb + PART8 + b_base + np * (16 * ROWB8) + kso);
                B2[np * 2][0] = r0; B2[np * 2][1] = r1;
                B2[np * 2 + 1][0] = r2; B2[np * 2 + 1][1] = r3;
            }
            // pass q1*p1 -> ACC0
            #pragma unroll
            for (int mt = 0; mt < 2; mt++)
                #pragma unroll
                for (int nt = 0; nt < 4; nt++)
                    mma_s8(acc0[mt][nt], A1[mt], B1[nt]);
            // pass q1*p2 -> ACC1
            #pragma unroll
            for (int mt = 0; mt < 2; mt++)
                #pragma unroll
                for (int nt = 0; nt < 4; nt++)
                    mma_s8(acc1[mt][nt], A1[mt], B2[nt]);
            // pass q2*p1 -> ACC1
            #pragma unroll
            for (int mt = 0; mt < 2; mt++)
                #pragma unroll
                for (int nt = 0; nt < 4; nt++)
                    mma_s8(acc1[mt][nt], A2[mt], B1[nt]);
        }
        __syncthreads();
    }

    // ------------------------------ epilogue -------------------------------
    const int lr = lane >> 2;
    const int lc = (lane & 3) * 2;
    constexpr float R254 = 1.f / 254.f;

    if (MODE == 0) {
        #pragma unroll
        for (int mt = 0; mt < 2; mt++) {
            #pragma unroll
            for (int h = 0; h < 2; h++) {
                const int row = by * 128 + warp_m * 32 + mt * 16 + h * 8 + lr;
                const float uu = g_ux[row];
                const float x2v = g_x2[row];
                float tmn = 3.0e38f;
                #pragma unroll
                for (int nt = 0; nt < 4; nt++) {
                    const int col = bx * 128 + warp_n * 32 + nt * 8 + lc;
                    const int i0 = h * 2;
                    float d0 = uu * g_vc[col] *
                               ((float)acc0[mt][nt][i0] + (float)acc1[mt][nt][i0] * R254);
                    float d1 = uu * g_vc[col + 1] *
                               ((float)acc0[mt][nt][i0 + 1] + (float)acc1[mt][nt][i0 + 1] * R254);
                    float sq0 = x2v + g_c2[col]     - 2.f * d0;
                    float sq1 = x2v + g_c2[col + 1] - 2.f * d1;
                    float t0 = beta[col]     * sqrtf(fmaxf(sq0, 0.f));
                    float t1 = beta[col + 1] * sqrtf(fmaxf(sq1, 0.f));
                    *reinterpret_cast<float2*>(&g_t[(size_t)row * C_ + col]) =
                        make_float2(t0, t1);
                    tmn = fminf(tmn, fminf(t0, t1));
                }
                tmn = fminf(tmn, __shfl_xor_sync(0xffffffffu, tmn, 1));
                tmn = fminf(tmn, __shfl_xor_sync(0xffffffffu, tmn, 2));
                if ((lane & 3) == 0)
                    atomicMin(&g_tmin[row], __float_as_int(tmn));
            }
        }
    } else {
        #pragma unroll
        for (int mt = 0; mt < 2; mt++) {
            #pragma unroll
            for (int h = 0; h < 2; h++) {
                const int row = by * 128 + warp_m * 32 + mt * 16 + h * 8 + lr;
                const float inv = (1.f / 127.f) / g_rowsum[row];
                #pragma unroll
                for (int nt = 0; nt < 4; nt++) {
                    const int col = bx * 128 + warp_n * 32 + nt * 8 + lc;
                    if (col < K_) {
                        const int i0 = h * 2;
                        float s0 = g_wk[col] * inv;
                        float s1 = g_wk[col + 1] * inv;
                        float2 bb = *reinterpret_cast<const float2*>(&bias[col]);
                        float2 o;
                        o.x = s0 * ((float)acc0[mt][nt][i0] +
                                    (float)acc1[mt][nt][i0] * R254) + bb.x;
                        o.y = s1 * ((float)acc0[mt][nt][i0 + 1] +
                                    (float)acc1[mt][nt][i0 + 1] * R254) + bb.y;
                        *reinterpret_cast<float2*>(&out[(size_t)row * K_ + col]) = o;
                    }
                }
            }
        }
    }
}

// ---------------------------------------------------------------------------
extern "C" void kernel_launch(void* const* d_in, const int* in_sizes, int n_in,
                              void* d_out, int out_size) {
    const float* x       = (const float*)d_in[0];
    const float* centers = (const float*)d_in[1];
    const float* beta    = (const float*)d_in[2];
    const float* W       = (const float*)d_in[3];
    const float* bias    = (const float*)d_in[4];
    float* out = (float*)d_out;

    int8_t *xq1, *xq2, *cq1, *cq2, *wq1, *wq2, *aq1, *aq2;
    float* tarr;
    cudaGetSymbolAddress((void**)&xq1, g_xq1);
    cudaGetSymbolAddress((void**)&xq2, g_xq2);
    cudaGetSymbolAddress((void**)&cq1, g_cq1);
    cudaGetSymbolAddress((void**)&cq2, g_cq2);
    cudaGetSymbolAddress((void**)&wq1, g_wq1);
    cudaGetSymbolAddress((void**)&wq2, g_wq2);
    cudaGetSymbolAddress((void**)&aq1, g_aq1);
    cudaGetSymbolAddress((void**)&aq2, g_aq2);
    cudaGetSymbolAddress((void**)&tarr, g_t);

    cudaFuncSetAttribute(gemm_s8_kernel<D_, 0>,
                         cudaFuncAttributeMaxDynamicSharedMemorySize, SMEM8);
    cudaFuncSetAttribute(gemm_s8_kernel<C_, 1>,
                         cudaFuncAttributeMaxDynamicSharedMemorySize, SMEM8);

    quant_kernel<D_, 0><<<B_, 256>>>(x, xq1, xq2);
    quant_kernel<D_, 1><<<C_, 256>>>(centers, cq1, cq2);
    quant_kernel<C_, 2><<<KPAD_, 256>>>(W, wq1, wq2);

    dim3 g1(C_ / 128, B_ / 128);            // (32, 64)
    gemm_s8_kernel<D_, 0><<<g1, 512, SMEM8>>>(xq1, xq2, cq1, cq2,
                                              beta, bias, out);

    actquant_kernel<<<B_, 256>>>(tarr, aq1, aq2);

    dim3 g2(KPAD_ / 128, B_ / 128);         // (8, 64)
    gemm_s8_kernel<C_, 1><<<g2, 512, SMEM8>>>(aq1, aq2, wq1, wq2,
                                              beta, bias, out);
}

// round 7
// speedup vs baseline: 3.7015x; 3.7015x over previous
#include <cuda_runtime.h>
#include <cuda_bf16.h>
#include <cuda_fp16.h>
#include <stdint.h>
#include <math.h>

#define B_ 8192
#define D_ 2048
#define C_ 4096
#define K_ 1000
#define KPAD_ 1024

// ---- GEMM2 (bf16 3-pass) smem geometry: 64B data + 16B pad per row ----
#define ROWB 80
#define PART_BYTES (128 * ROWB)    // 10240
#define BUF_BYTES (4 * PART_BYTES) // 40960
#define GEMM2_SMEM (2 * BUF_BYTES) // 81920

// ---- GEMM1 (fp16 2-pass) smem geometry: 3 parts, 3 stages ----
#define S1_PART 10240              // 128 rows x 80B
#define S1_STAGE (3 * S1_PART)     // 30720
#define S1_SMEM (3 * S1_STAGE)     // 92160

// ---------------------------------------------------------------------------
// Device scratch
// ---------------------------------------------------------------------------
__device__ __align__(128) __half g_xh[(size_t)B_ * D_];
__device__ __align__(128) __half g_chh[(size_t)C_ * D_], g_chl[(size_t)C_ * D_];
__device__ __align__(128) __nv_bfloat16 g_Whi[(size_t)KPAD_ * C_], g_Wlo[(size_t)KPAD_ * C_];
__device__ __align__(128) __nv_bfloat16 g_ahi[(size_t)B_ * C_], g_alo[(size_t)B_ * C_];
__device__ float g_x2[B_], g_c2[C_], g_rowsum[B_];

// ---------------------------------------------------------------------------
// PTX helpers
// ---------------------------------------------------------------------------
__device__ __forceinline__ uint32_t smem_u32(const void* p) {
    uint32_t a;
    asm("{ .reg .u64 t; cvta.to.shared.u64 t, %1; cvt.u32.u64 %0, t; }"
        : "=r"(a) : "l"(p));
    return a;
}

__device__ __forceinline__ void ldsm_x4(uint32_t& r0, uint32_t& r1, uint32_t& r2,
                                        uint32_t& r3, uint32_t addr) {
    asm volatile("ldmatrix.sync.aligned.m8n8.x4.shared.b16 {%0,%1,%2,%3}, [%4];"
                 : "=r"(r0), "=r"(r1), "=r"(r2), "=r"(r3) : "r"(addr));
}

__device__ __forceinline__ void mma_bf16(float c[4], const uint32_t a[4],
                                         const uint32_t b[2]) {
    asm volatile(
        "mma.sync.aligned.m16n8k16.row.col.f32.bf16.bf16.f32 "
        "{%0,%1,%2,%3}, {%4,%5,%6,%7}, {%8,%9}, {%0,%1,%2,%3};"
        : "+f"(c[0]), "+f"(c[1]), "+f"(c[2]), "+f"(c[3])
        : "r"(a[0]), "r"(a[1]), "r"(a[2]), "r"(a[3]), "r"(b[0]), "r"(b[1]));
}

__device__ __forceinline__ void mma_f16(float c[4], const uint32_t a[4],
                                        const uint32_t b[2]) {
    asm volatile(
        "mma.sync.aligned.m16n8k16.row.col.f32.f16.f16.f32 "
        "{%0,%1,%2,%3}, {%4,%5,%6,%7}, {%8,%9}, {%0,%1,%2,%3};"
        : "+f"(c[0]), "+f"(c[1]), "+f"(c[2]), "+f"(c[3])
        : "r"(a[0]), "r"(a[1]), "r"(a[2]), "r"(a[3]), "r"(b[0]), "r"(b[1]));
}

__device__ __forceinline__ void cp16(uint32_t dst, const void* src) {
    asm volatile("cp.async.cg.shared.global [%0], [%1], 16;"
                 :: "r"(dst), "l"(src) : "memory");
}
#define CP_COMMIT() asm volatile("cp.async.commit_group;" ::: "memory")
template <int N>
__device__ __forceinline__ void cp_wait() {
    asm volatile("cp.async.wait_group %0;" :: "n"(N) : "memory");
}

// ---------------------------------------------------------------------------
// Prologue: x -> fp16 (single digit) + x2 (+ zero rowsum)
// ---------------------------------------------------------------------------
__global__ void splitx_kernel(const float* __restrict__ x, __half* __restrict__ xh) {
    const int row = blockIdx.x;
    const float4* p = reinterpret_cast<const float4*>(x + (size_t)row * D_);
    float s = 0.f;
    for (int i = threadIdx.x; i < D_ / 4; i += blockDim.x) {
        float4 v = p[i];
        s += v.x * v.x + v.y * v.y + v.z * v.z + v.w * v.w;
        __half h[4] = {__float2half(v.x), __float2half(v.y),
                       __float2half(v.z), __float2half(v.w)};
        *reinterpret_cast<uint2*>(xh + (size_t)row * D_ + i * 4) =
            *reinterpret_cast<uint2*>(h);
    }
    #pragma unroll
    for (int o = 16; o; o >>= 1) s += __shfl_xor_sync(0xffffffffu, s, o);
    __shared__ float ws[8];
    if ((threadIdx.x & 31) == 0) ws[threadIdx.x >> 5] = s;
    __syncthreads();
    if (threadIdx.x == 0) {
        float t = 0.f;
        #pragma unroll
        for (int i = 0; i < 8; i++) t += ws[i];
        g_x2[row] = t;
        g_rowsum[row] = 0.f;
    }
}

// centers -> fp16 hi/lo + c2
__global__ void splitc_kernel(const float* __restrict__ cen,
                              __half* __restrict__ chh, __half* __restrict__ chl) {
    const int row = blockIdx.x;
    const float4* p = reinterpret_cast<const float4*>(cen + (size_t)row * D_);
    float s = 0.f;
    for (int i = threadIdx.x; i < D_ / 4; i += blockDim.x) {
        float4 v = p[i];
        float f[4] = {v.x, v.y, v.z, v.w};
        s += f[0] * f[0] + f[1] * f[1] + f[2] * f[2] + f[3] * f[3];
        __half h[4], l[4];
        #pragma unroll
        for (int j = 0; j < 4; j++) {
            h[j] = __float2half(f[j]);
            l[j] = __float2half(f[j] - __half2float(h[j]));
        }
        *reinterpret_cast<uint2*>(chh + (size_t)row * D_ + i * 4) =
            *reinterpret_cast<uint2*>(h);
        *reinterpret_cast<uint2*>(chl + (size_t)row * D_ + i * 4) =
            *reinterpret_cast<uint2*>(l);
    }
    #pragma unroll
    for (int o = 16; o; o >>= 1) s += __shfl_xor_sync(0xffffffffu, s, o);
    __shared__ float ws[8];
    if ((threadIdx.x & 31) == 0) ws[threadIdx.x >> 5] = s;
    __syncthreads();
    if (threadIdx.x == 0) {
        float t = 0.f;
        #pragma unroll
        for (int i = 0; i < 8; i++) t += ws[i];
        g_c2[row] = t;
    }
}

// W -> bf16 hi/lo, zero-padded to KPAD_ rows
__global__ void splitW_kernel(const float* __restrict__ W) {
    int i = blockIdx.x * blockDim.x + threadIdx.x;
    if (i >= KPAD_ * C_ / 4) return;
    int r = i >> 10;
    int c0 = (i & 1023) * 4;
    float f[4] = {0.f, 0.f, 0.f, 0.f};
    if (r < K_) {
        float4 v = *reinterpret_cast<const float4*>(W + (size_t)r * C_ + c0);
        f[0] = v.x; f[1] = v.y; f[2] = v.z; f[3] = v.w;
    }
    __nv_bfloat16 h[4], l[4];
    #pragma unroll
    for (int j = 0; j < 4; j++) {
        h[j] = __float2bfloat16(f[j]);
        l[j] = __float2bfloat16(f[j] - __bfloat162float(h[j]));
    }
    *reinterpret_cast<uint2*>(g_Whi + (size_t)r * C_ + c0) = *reinterpret_cast<uint2*>(h);
    *reinterpret_cast<uint2*>(g_Wlo + (size_t)r * C_ + c0) = *reinterpret_cast<uint2*>(l);
}

// ---------------------------------------------------------------------------
// GEMM1: fp16 2-pass (xh*ch + xh*cl), 128x128 CTA, 8 warps (64x32 warp tile),
// K-chunk 32, 3-stage cp.async pipeline, ONE __syncthreads per chunk,
// 2 CTAs/SM. Epilogue: RBF + bf16 hi/lo act + rowsum atomics.
// ---------------------------------------------------------------------------
__global__ __launch_bounds__(256, 2) void gemm1_f16_kernel(
    const __half* __restrict__ Xh, const __half* __restrict__ Chh,
    const __half* __restrict__ Chl, const float* __restrict__ beta)
{
    constexpr int KDIM = D_;
    constexpr int NCH = KDIM / 32;
    extern __shared__ char smem[];
    const uint32_t sb = smem_u32(smem);
    const int tid = threadIdx.x;
    const int w = tid >> 5, lane = tid & 31;
    const int warp_m = w >> 2, warp_n = w & 3;
    const int bx = blockIdx.x, by = blockIdx.y;

    // loader: 3 parts; each thread covers rows (tid>>2) and (tid>>2)+64, granule tid&3
    const int lrow = tid >> 2, lg = tid & 3;
    const __half* srcP0 = Xh  + (size_t)(by * 128 + lrow) * KDIM + lg * 8;
    const __half* srcP1 = Chh + (size_t)(bx * 128 + lrow) * KDIM + lg * 8;
    const __half* srcP2 = Chl + (size_t)(bx * 128 + lrow) * KDIM + lg * 8;
    const uint32_t d0 = 0 * S1_PART + lrow * ROWB + lg * 16;
    const uint32_t d1 = 1 * S1_PART + lrow * ROWB + lg * 16;
    const uint32_t d2 = 2 * S1_PART + lrow * ROWB + lg * 16;

    float acc[4][4][4];
    #pragma unroll
    for (int mt = 0; mt < 4; mt++)
        #pragma unroll
        for (int nt = 0; nt < 4; nt++)
            #pragma unroll
            for (int q = 0; q < 4; q++) acc[mt][nt][q] = 0.f;

#define S1_ISSUE(stage, c) do {                                              \
        const uint32_t stb_ = sb + (stage) * S1_STAGE;                       \
        const int co_ = (c) * 32;                                            \
        cp16(stb_ + d0, srcP0 + co_);                                        \
        cp16(stb_ + d0 + 64 * ROWB, srcP0 + (size_t)64 * KDIM + co_);        \
        cp16(stb_ + d1, srcP1 + co_);                                        \
        cp16(stb_ + d1 + 64 * ROWB, srcP1 + (size_t)64 * KDIM + co_);        \
        cp16(stb_ + d2, srcP2 + co_);                                        \
        cp16(stb_ + d2 + 64 * ROWB, srcP2 + (size_t)64 * KDIM + co_);        \
        CP_COMMIT();                                                         \
    } while (0)

    S1_ISSUE(0, 0);
    S1_ISSUE(1, 1);

    const uint32_t aoff = (uint32_t)(warp_m * 64 + (lane & 15)) * ROWB +
                          (uint32_t)((lane >> 4) << 3) * 2;
    const uint32_t boff = (uint32_t)(warp_n * 32 + (lane & 7) + ((lane >> 4) << 3)) * ROWB +
                          (uint32_t)(lane & 8) * 2;

    int st = 0, ld = 2;
    #pragma unroll 1
    for (int c = 0; c < NCH; c++) {
        if (c + 1 < NCH) cp_wait<1>(); else cp_wait<0>();
        __syncthreads();
        if (c + 2 < NCH) S1_ISSUE(ld, c + 2);

        const uint32_t bufb = sb + st * S1_STAGE;
        #pragma unroll
        for (int ks = 0; ks < 2; ks++) {
            const uint32_t kso = ks * 32;
            uint32_t AH[4][4], BH[4][2], BL[4][2];
            #pragma unroll
            for (int mt = 0; mt < 4; mt++)
                ldsm_x4(AH[mt][0], AH[mt][1], AH[mt][2], AH[mt][3],
                        bufb + aoff + kso + mt * 16 * ROWB);
            #pragma unroll
            for (int np = 0; np < 2; np++) {
                uint32_t r0, r1, r2, r3;
                ldsm_x4(r0, r1, r2, r3,
                        bufb + S1_PART + boff + kso + np * 16 * ROWB);
                BH[np * 2][0] = r0; BH[np * 2][1] = r1;
                BH[np * 2 + 1][0] = r2; BH[np * 2 + 1][1] = r3;
                ldsm_x4(r0, r1, r2, r3,
                        bufb + 2 * S1_PART + boff + kso + np * 16 * ROWB);
                BL[np * 2][0] = r0; BL[np * 2][1] = r1;
                BL[np * 2 + 1][0] = r2; BL[np * 2 + 1][1] = r3;
            }
            #pragma unroll
            for (int mt = 0; mt < 4; mt++)
                #pragma unroll
                for (int nt = 0; nt < 4; nt++)
                    mma_f16(acc[mt][nt], AH[mt], BH[nt]);
            #pragma unroll
            for (int mt = 0; mt < 4; mt++)
                #pragma unroll
                for (int nt = 0; nt < 4; nt++)
                    mma_f16(acc[mt][nt], AH[mt], BL[nt]);
        }
        st = (st + 1 == 3) ? 0 : st + 1;
        ld = (ld + 1 == 3) ? 0 : ld + 1;
    }

    // ---- epilogue: RBF + bf16 hi/lo act + rowsum ----
    const int lr = lane >> 2;
    const int lc = (lane & 3) * 2;
    #pragma unroll
    for (int mt = 0; mt < 4; mt++) {
        #pragma unroll
        for (int h = 0; h < 2; h++) {
            const int row = by * 128 + warp_m * 64 + mt * 16 + h * 8 + lr;
            const float x2v = g_x2[row];
            float rsum = 0.f;
            #pragma unroll
            for (int nt = 0; nt < 4; nt++) {
                const int col = bx * 128 + warp_n * 32 + nt * 8 + lc;
                const float dd0 = acc[mt][nt][h * 2 + 0];
                const float dd1 = acc[mt][nt][h * 2 + 1];
                float sq0 = x2v + g_c2[col]     - 2.f * dd0;
                float sq1 = x2v + g_c2[col + 1] - 2.f * dd1;
                float v0 = __expf(-beta[col]     * sqrtf(fmaxf(sq0, 0.f)));
                float v1 = __expf(-beta[col + 1] * sqrtf(fmaxf(sq1, 0.f)));
                rsum += v0 + v1;
                __nv_bfloat16 h0 = __float2bfloat16(v0);
                __nv_bfloat16 h1 = __float2bfloat16(v1);
                __nv_bfloat16 l0 = __float2bfloat16(v0 - __bfloat162float(h0));
                __nv_bfloat16 l1 = __float2bfloat16(v1 - __bfloat162float(h1));
                uint32_t hp = (uint32_t)__bfloat16_as_ushort(h0) |
                              ((uint32_t)__bfloat16_as_ushort(h1) << 16);
                uint32_t lp = (uint32_t)__bfloat16_as_ushort(l0) |
                              ((uint32_t)__bfloat16_as_ushort(l1) << 16);
                *reinterpret_cast<uint32_t*>(&g_ahi[(size_t)row * C_ + col]) = hp;
                *reinterpret_cast<uint32_t*>(&g_alo[(size_t)row * C_ + col]) = lp;
            }
            rsum += __shfl_xor_sync(0xffffffffu, rsum, 1);
            rsum += __shfl_xor_sync(0xffffffffu, rsum, 2);
            if ((lane & 3) == 0) atomicAdd(&g_rowsum[row], rsum);
        }
    }
#undef S1_ISSUE
}

// ---------------------------------------------------------------------------
// GEMM2: bf16 3-pass (act hi/lo x W hi/lo, drop lo*lo) — R5 structure:
// 128x128 CTA, 8 warps, K-chunk 32, 2-stage cp.async, 2 CTAs/SM,
// A-register reload trick. Epilogue: normalize + bias.
// ---------------------------------------------------------------------------
__global__ __launch_bounds__(256, 2) void gemm2_bf16_kernel(
    const __nv_bfloat16* __restrict__ Ahi, const __nv_bfloat16* __restrict__ Alo,
    const __nv_bfloat16* __restrict__ Bhi, const __nv_bfloat16* __restrict__ Blo,
    const float* __restrict__ bias, float* __restrict__ out)
{
    constexpr int KDIM = C_;
    extern __shared__ char smem[];
    const uint32_t sb = smem_u32(smem);
    const int tid = threadIdx.x;
    const int w = tid >> 5, lane = tid & 31;
    const int warp_m = w >> 2, warp_n = w & 3;
    const int bx = blockIdx.x, by = blockIdx.y;

    const int part = tid >> 6;
    const int l6 = tid & 63;
    const int row0 = l6 >> 2;
    const int gg = l6 & 3;
    const __nv_bfloat16* srcBase =
        (part == 0) ? Ahi : (part == 1) ? Alo : (part == 2) ? Bhi : Blo;
    const int rbase = (part < 2) ? by * 128 : bx * 128;
    const __nv_bfloat16* src0 = srcBase + (size_t)(rbase + row0) * KDIM + gg * 8;
    const uint32_t dst0 = sb + part * PART_BYTES + row0 * ROWB + gg * 16;

    float acc[4][4][4];
    #pragma unroll
    for (int mt = 0; mt < 4; mt++)
        #pragma unroll
        for (int nt = 0; nt < 4; nt++)
            #pragma unroll
            for (int q = 0; q < 4; q++) acc[mt][nt][q] = 0.f;

    constexpr int NCH = KDIM / 32;

    {
        #pragma unroll
        for (int j = 0; j < 8; j++)
            cp16(dst0 + j * 16 * ROWB, src0 + (size_t)(j * 16) * KDIM);
        CP_COMMIT();
    }

    const uint32_t aoff = (uint32_t)(warp_m * 64 + (lane & 15)) * ROWB +
                          (uint32_t)((lane >> 4) << 3) * 2;
    const uint32_t boff = (uint32_t)(warp_n * 32 + (lane & 7) + ((lane >> 4) << 3)) * ROWB +
                          (uint32_t)(lane & 8) * 2;

    #pragma unroll 1
    for (int c = 0; c < NCH; c++) {
        if (c + 1 < NCH) {
            const __nv_bfloat16* s = src0 + (size_t)(c + 1) * 32;
            const uint32_t d = dst0 + ((c + 1) & 1) * BUF_BYTES;
            #pragma unroll
            for (int j = 0; j < 8; j++)
                cp16(d + j * 16 * ROWB, s + (size_t)(j * 16) * KDIM);
            CP_COMMIT();
            cp_wait<1>();
        } else {
            cp_wait<0>();
        }
        __syncthreads();

        const uint32_t bufb = sb + (c & 1) * BUF_BYTES;
        #pragma unroll
        for (int ks = 0; ks < 2; ks++) {
            const uint32_t kso = ks * 32;
            uint32_t A[4][4];
            uint32_t BH[4][2], BL[4][2];
            #pragma unroll
            for (int mt = 0; mt < 4; mt++)
                ldsm_x4(A[mt][0], A[mt][1], A[mt][2], A[mt][3],
                        bufb + aoff + kso + mt * 16 * ROWB);
            #pragma unroll
            for (int np = 0; np < 2; np++) {
                uint32_t r0, r1, r2, r3;
                ldsm_x4(r0, r1, r2, r3,
                        bufb + 2 * PART_BYTES + boff + kso + np * 16 * ROWB);
                BH[np * 2][0] = r0; BH[np * 2][1] = r1;
                BH[np * 2 + 1][0] = r2; BH[np * 2 + 1][1] = r3;
                ldsm_x4(r0, r1, r2, r3,
                        bufb + 3 * PART_BYTES + boff + kso + np * 16 * ROWB);
                BL[np * 2][0] = r0; BL[np * 2][1] = r1;
                BL[np * 2 + 1][0] = r2; BL[np * 2 + 1][1] = r3;
            }
            #pragma unroll
            for (int mt = 0; mt < 4; mt++)
                #pragma unroll
                for (int nt = 0; nt < 4; nt++)
                    mma_bf16(acc[mt][nt], A[mt], BH[nt]);
            #pragma unroll
            for (int mt = 0; mt < 4; mt++)
                #pragma unroll
                for (int nt = 0; nt < 4; nt++)
                    mma_bf16(acc[mt][nt], A[mt], BL[nt]);
            #pragma unroll
            for (int mt = 0; mt < 4; mt++)
                ldsm_x4(A[mt][0], A[mt][1], A[mt][2], A[mt][3],
                        bufb + PART_BYTES + aoff + kso + mt * 16 * ROWB);
            #pragma unroll
            for (int mt = 0; mt < 4; mt++)
                #pragma unroll
                for (int nt = 0; nt < 4; nt++)
                    mma_bf16(acc[mt][nt], A[mt], BH[nt]);
        }
        __syncthreads();
    }

    const int lr = lane >> 2;
    const int lc = (lane & 3) * 2;
    #pragma unroll
    for (int mt = 0; mt < 4; mt++) {
        #pragma unroll
        for (int h = 0; h < 2; h++) {
            const int row = by * 128 + warp_m * 64 + mt * 16 + h * 8 + lr;
            const float inv = 1.0f / g_rowsum[row];
            #pragma unroll
            for (int nt = 0; nt < 4; nt++) {
                const int col = bx * 128 + warp_n * 32 + nt * 8 + lc;
                if (col < K_) {
                    float2 bb = *reinterpret_cast<const float2*>(&bias[col]);
                    float2 o;
                    o.x = acc[mt][nt][h * 2 + 0] * inv + bb.x;
                    o.y = acc[mt][nt][h * 2 + 1] * inv + bb.y;
                    *reinterpret_cast<float2*>(&out[(size_t)row * K_ + col]) = o;
                }
            }
        }
    }
}

// ---------------------------------------------------------------------------
extern "C" void kernel_launch(void* const* d_in, const int* in_sizes, int n_in,
                              void* d_out, int out_size) {
    const float* x       = (const float*)d_in[0];
    const float* centers = (const float*)d_in[1];
    const float* beta    = (const float*)d_in[2];
    const float* W       = (const float*)d_in[3];
    const float* bias    = (const float*)d_in[4];
    float* out = (float*)d_out;

    __half *xh, *chh, *chl;
    __nv_bfloat16 *ahi, *alo, *whi, *wlo;
    cudaGetSymbolAddress((void**)&xh,  g_xh);
    cudaGetSymbolAddress((void**)&chh, g_chh);
    cudaGetSymbolAddress((void**)&chl, g_chl);
    cudaGetSymbolAddress((void**)&ahi, g_ahi);
    cudaGetSymbolAddress((void**)&alo, g_alo);
    cudaGetSymbolAddress((void**)&whi, g_Whi);
    cudaGetSymbolAddress((void**)&wlo, g_Wlo);

    cudaFuncSetAttribute(gemm1_f16_kernel,
                         cudaFuncAttributeMaxDynamicSharedMemorySize, S1_SMEM);
    cudaFuncSetAttribute(gemm2_bf16_kernel,
                         cudaFuncAttributeMaxDynamicSharedMemorySize, GEMM2_SMEM);

    splitx_kernel<<<B_, 256>>>(x, xh);
    splitc_kernel<<<C_, 256>>>(centers, chh, chl);
    {
        int n4 = KPAD_ * C_ / 4;
        splitW_kernel<<<(n4 + 255) / 256, 256>>>(W);
    }

    dim3 g1(C_ / 128, B_ / 128);            // (32, 64)
    gemm1_f16_kernel<<<g1, 256, S1_SMEM>>>(xh, chh, chl, beta);

    dim3 g2(KPAD_ / 128, B_ / 128);         // (8, 64)
    gemm2_bf16_kernel<<<g2, 256, GEMM2_SMEM>>>(ahi, alo, whi, wlo, bias, out);
}

// round 8
// speedup vs baseline: 4.3590x; 1.1776x over previous
#include <cuda_runtime.h>
#include <cuda_fp16.h>
#include <stdint.h>
#include <math.h>

#define B_ 8192
#define D_ 2048
#define C_ 4096
#define K_ 1000
#define KPAD_ 1024

// smem geometry: 128 rows x (64B data + 16B pad); 3 parts, 3 stages
#define ROWB 80
#define S_PART 10240               // 128 * 80
#define S_STAGE (3 * S_PART)       // 30720
#define S_SMEM (3 * S_STAGE)       // 92160

// ---------------------------------------------------------------------------
// Device scratch
// ---------------------------------------------------------------------------
__device__ __align__(128) __half g_xh[(size_t)B_ * D_];
__device__ __align__(128) __half g_chh[(size_t)C_ * D_], g_chl[(size_t)C_ * D_];
__device__ __align__(128) __half g_whh[(size_t)KPAD_ * C_], g_whl[(size_t)KPAD_ * C_];
__device__ __align__(128) __half g_ah[(size_t)B_ * C_];
__device__ float g_x2[B_], g_c2[C_], g_rowsum[B_];
__device__ float g_c2mean;

// ---------------------------------------------------------------------------
// PTX helpers
// ---------------------------------------------------------------------------
__device__ __forceinline__ uint32_t smem_u32(const void* p) {
    uint32_t a;
    asm("{ .reg .u64 t; cvta.to.shared.u64 t, %1; cvt.u32.u64 %0, t; }"
        : "=r"(a) : "l"(p));
    return a;
}

__device__ __forceinline__ void ldsm_x4(uint32_t& r0, uint32_t& r1, uint32_t& r2,
                                        uint32_t& r3, uint32_t addr) {
    asm volatile("ldmatrix.sync.aligned.m8n8.x4.shared.b16 {%0,%1,%2,%3}, [%4];"
                 : "=r"(r0), "=r"(r1), "=r"(r2), "=r"(r3) : "r"(addr));
}

__device__ __forceinline__ void mma_f16(float c[4], const uint32_t a[4],
                                        const uint32_t b[2]) {
    asm volatile(
        "mma.sync.aligned.m16n8k16.row.col.f32.f16.f16.f32 "
        "{%0,%1,%2,%3}, {%4,%5,%6,%7}, {%8,%9}, {%0,%1,%2,%3};"
        : "+f"(c[0]), "+f"(c[1]), "+f"(c[2]), "+f"(c[3])
        : "r"(a[0]), "r"(a[1]), "r"(a[2]), "r"(a[3]), "r"(b[0]), "r"(b[1]));
}

__device__ __forceinline__ void cp16(uint32_t dst, const void* src) {
    asm volatile("cp.async.cg.shared.global [%0], [%1], 16;"
                 :: "r"(dst), "l"(src) : "memory");
}
#define CP_COMMIT() asm volatile("cp.async.commit_group;" ::: "memory")
template <int N>
__device__ __forceinline__ void cp_wait() {
    asm volatile("cp.async.wait_group %0;" :: "n"(N) : "memory");
}

// ---------------------------------------------------------------------------
// Prologue kernels
// ---------------------------------------------------------------------------
__global__ void splitx_kernel(const float* __restrict__ x, __half* __restrict__ xh) {
    const int row = blockIdx.x;
    const float4* p = reinterpret_cast<const float4*>(x + (size_t)row * D_);
    float s = 0.f;
    for (int i = threadIdx.x; i < D_ / 4; i += blockDim.x) {
        float4 v = p[i];
        s += v.x * v.x + v.y * v.y + v.z * v.z + v.w * v.w;
        __half h[4] = {__float2half(v.x), __float2half(v.y),
                       __float2half(v.z), __float2half(v.w)};
        *reinterpret_cast<uint2*>(xh + (size_t)row * D_ + i * 4) =
            *reinterpret_cast<uint2*>(h);
    }
    #pragma unroll
    for (int o = 16; o; o >>= 1) s += __shfl_xor_sync(0xffffffffu, s, o);
    __shared__ float ws[8];
    if ((threadIdx.x & 31) == 0) ws[threadIdx.x >> 5] = s;
    __syncthreads();
    if (threadIdx.x == 0) {
        float t = 0.f;
        #pragma unroll
        for (int i = 0; i < 8; i++) t += ws[i];
        g_x2[row] = t;
        g_rowsum[row] = 0.f;
    }
}

__global__ void splitc_kernel(const float* __restrict__ cen,
                              __half* __restrict__ chh, __half* __restrict__ chl) {
    const int row = blockIdx.x;
    const float4* p = reinterpret_cast<const float4*>(cen + (size_t)row * D_);
    float s = 0.f;
    for (int i = threadIdx.x; i < D_ / 4; i += blockDim.x) {
        float4 v = p[i];
        float f[4] = {v.x, v.y, v.z, v.w};
        s += f[0] * f[0] + f[1] * f[1] + f[2] * f[2] + f[3] * f[3];
        __half h[4], l[4];
        #pragma unroll
        for (int j = 0; j < 4; j++) {
            h[j] = __float2half(f[j]);
            l[j] = __float2half(f[j] - __half2float(h[j]));
        }
        *reinterpret_cast<uint2*>(chh + (size_t)row * D_ + i * 4) =
            *reinterpret_cast<uint2*>(h);
        *reinterpret_cast<uint2*>(chl + (size_t)row * D_ + i * 4) =
            *reinterpret_cast<uint2*>(l);
    }
    #pragma unroll
    for (int o = 16; o; o >>= 1) s += __shfl_xor_sync(0xffffffffu, s, o);
    __shared__ float ws[8];
    if ((threadIdx.x & 31) == 0) ws[threadIdx.x >> 5] = s;
    __syncthreads();
    if (threadIdx.x == 0) {
        float t = 0.f;
        #pragma unroll
        for (int i = 0; i < 8; i++) t += ws[i];
        g_c2[row] = t;
    }
}

__global__ void c2mean_kernel() {
    float s = 0.f;
    for (int i = threadIdx.x; i < C_; i += 1024) s += g_c2[i];
    #pragma unroll
    for (int o = 16; o; o >>= 1) s += __shfl_xor_sync(0xffffffffu, s, o);
    __shared__ float ws[32];
    if ((threadIdx.x & 31) == 0) ws[threadIdx.x >> 5] = s;
    __syncthreads();
    if (threadIdx.x == 0) {
        float t = 0.f;
        #pragma unroll
        for (int i = 0; i < 32; i++) t += ws[i];
        g_c2mean = t * (1.f / C_);
    }
}

// W -> fp16 hi/lo, zero-padded to KPAD_ rows
__global__ void splitW_kernel(const float* __restrict__ W) {
    int i = blockIdx.x * blockDim.x + threadIdx.x;
    if (i >= KPAD_ * C_ / 4) return;
    int r = i >> 10;
    int c0 = (i & 1023) * 4;
    float f[4] = {0.f, 0.f, 0.f, 0.f};
    if (r < K_) {
        float4 v = *reinterpret_cast<const float4*>(W + (size_t)r * C_ + c0);
        f[0] = v.x; f[1] = v.y; f[2] = v.z; f[3] = v.w;
    }
    __half h[4], l[4];
    #pragma unroll
    for (int j = 0; j < 4; j++) {
        h[j] = __float2half(f[j]);
        l[j] = __float2half(f[j] - __half2float(h[j]));
    }
    *reinterpret_cast<uint2*>(g_whh + (size_t)r * C_ + c0) = *reinterpret_cast<uint2*>(h);
    *reinterpret_cast<uint2*>(g_whl + (size_t)r * C_ + c0) = *reinterpret_cast<uint2*>(l);
}

// ---------------------------------------------------------------------------
// fp16 2-pass GEMM (A x (B1 + B2)), 128x128 CTA, 8 warps (64x32 warp tiles),
// K-chunk 32, 3-stage cp.async pipeline, one __syncthreads per chunk, 2 CTAs/SM.
// MODE 0 (GEMM1): A=xh, B=centers hi/lo. Epilogue: shifted RBF ->
//                 a' = exp(s - beta*dist) fp16 + rowsum atomics.
// MODE 1 (GEMM2): A=a', B=W hi/lo. Epilogue: out = acc/rowsum + bias.
// ---------------------------------------------------------------------------
template <int KDIM, int MODE>
__global__ __launch_bounds__(256, 2) void gemm_f16_kernel(
    const __half* __restrict__ Ah, const __half* __restrict__ B1,
    const __half* __restrict__ B2, const float* __restrict__ beta,
    const float* __restrict__ bias, float* __restrict__ out)
{
    constexpr int NCH = KDIM / 32;
    extern __shared__ char smem[];
    const uint32_t sb = smem_u32(smem);
    const int tid = threadIdx.x;
    const int w = tid >> 5, lane = tid & 31;
    const int warp_m = w >> 2, warp_n = w & 3;
    const int bx = blockIdx.x, by = blockIdx.y;

    // loader: 3 parts; each thread covers rows (tid>>2), (tid>>2)+64, granule tid&3
    const int lrow = tid >> 2, lg = tid & 3;
    const __half* srcP0 = Ah + (size_t)(by * 128 + lrow) * KDIM + lg * 8;
    const __half* srcP1 = B1 + (size_t)(bx * 128 + lrow) * KDIM + lg * 8;
    const __half* srcP2 = B2 + (size_t)(bx * 128 + lrow) * KDIM + lg * 8;
    const uint32_t d0 = 0 * S_PART + lrow * ROWB + lg * 16;
    const uint32_t d1 = 1 * S_PART + lrow * ROWB + lg * 16;
    const uint32_t d2 = 2 * S_PART + lrow * ROWB + lg * 16;

    float acc[4][4][4];
    #pragma unroll
    for (int mt = 0; mt < 4; mt++)
        #pragma unroll
        for (int nt = 0; nt < 4; nt++)
            #pragma unroll
            for (int q = 0; q < 4; q++) acc[mt][nt][q] = 0.f;

#define S_ISSUE(stage, c) do {                                               \
        const uint32_t stb_ = sb + (stage) * S_STAGE;                        \
        const int co_ = (c) * 32;                                            \
        cp16(stb_ + d0, srcP0 + co_);                                        \
        cp16(stb_ + d0 + 64 * ROWB, srcP0 + (size_t)64 * KDIM + co_);        \
        cp16(stb_ + d1, srcP1 + co_);                                        \
        cp16(stb_ + d1 + 64 * ROWB, srcP1 + (size_t)64 * KDIM + co_);        \
        cp16(stb_ + d2, srcP2 + co_);                                        \
        cp16(stb_ + d2 + 64 * ROWB, srcP2 + (size_t)64 * KDIM + co_);        \
        CP_COMMIT();                                                         \
    } while (0)

    S_ISSUE(0, 0);
    S_ISSUE(1, 1);

    const uint32_t aoff = (uint32_t)(warp_m * 64 + (lane & 15)) * ROWB +
                          (uint32_t)((lane >> 4) << 3) * 2;
    const uint32_t boff = (uint32_t)(warp_n * 32 + (lane & 7) + ((lane >> 4) << 3)) * ROWB +
                          (uint32_t)(lane & 8) * 2;

    int st = 0, ld = 2;
    #pragma unroll 1
    for (int c = 0; c < NCH; c++) {
        if (c + 1 < NCH) cp_wait<1>(); else cp_wait<0>();
        __syncthreads();
        if (c + 2 < NCH) S_ISSUE(ld, c + 2);

        const uint32_t bufb = sb + st * S_STAGE;
        #pragma unroll
        for (int ks = 0; ks < 2; ks++) {
            const uint32_t kso = ks * 32;
            uint32_t AH[4][4], BH[4][2], BL[4][2];
            #pragma unroll
            for (int mt = 0; mt < 4; mt++)
                ldsm_x4(AH[mt][0], AH[mt][1], AH[mt][2], AH[mt][3],
                        bufb + aoff + kso + mt * 16 * ROWB);
            #pragma unroll
            for (int np = 0; np < 2; np++) {
                uint32_t r0, r1, r2, r3;
                ldsm_x4(r0, r1, r2, r3,
                        bufb + S_PART + boff + kso + np * 16 * ROWB);
                BH[np * 2][0] = r0; BH[np * 2][1] = r1;
                BH[np * 2 + 1][0] = r2; BH[np * 2 + 1][1] = r3;
                ldsm_x4(r0, r1, r2, r3,
                        bufb + 2 * S_PART + boff + kso + np * 16 * ROWB);
                BL[np * 2][0] = r0; BL[np * 2][1] = r1;
                BL[np * 2 + 1][0] = r2; BL[np * 2 + 1][1] = r3;
            }
            #pragma unroll
            for (int mt = 0; mt < 4; mt++)
                #pragma unroll
                for (int nt = 0; nt < 4; nt++)
                    mma_f16(acc[mt][nt], AH[mt], BH[nt]);
            #pragma unroll
            for (int mt = 0; mt < 4; mt++)
                #pragma unroll
                for (int nt = 0; nt < 4; nt++)
                    mma_f16(acc[mt][nt], AH[mt], BL[nt]);
        }
        st = (st + 1 == 3) ? 0 : st + 1;
        ld = (ld + 1 == 3) ? 0 : ld + 1;
    }
#undef S_ISSUE

    // ------------------------------ epilogue -------------------------------
    const int lr = lane >> 2;
    const int lc = (lane & 3) * 2;

    if (MODE == 0) {
        const float c2m = g_c2mean;
        #pragma unroll
        for (int mt = 0; mt < 4; mt++) {
            #pragma unroll
            for (int h = 0; h < 2; h++) {
                const int row = by * 128 + warp_m * 64 + mt * 16 + h * 8 + lr;
                const float x2v = g_x2[row];
                const float shift = sqrtf(x2v + c2m) - 4.0f;   // per-row softmax shift
                float rsum = 0.f;
                #pragma unroll
                for (int nt = 0; nt < 4; nt++) {
                    const int col = bx * 128 + warp_n * 32 + nt * 8 + lc;
                    const float dd0 = acc[mt][nt][h * 2 + 0];
                    const float dd1 = acc[mt][nt][h * 2 + 1];
                    float sq0 = x2v + g_c2[col]     - 2.f * dd0;
                    float sq1 = x2v + g_c2[col + 1] - 2.f * dd1;
                    float e0 = fminf(shift - beta[col]     * sqrtf(fmaxf(sq0, 0.f)), 10.f);
                    float e1 = fminf(shift - beta[col + 1] * sqrtf(fmaxf(sq1, 0.f)), 10.f);
                    float v0 = __expf(e0);
                    float v1 = __expf(e1);
                    rsum += v0 + v1;
                    __half h0 = __float2half(v0);
                    __half h1 = __float2half(v1);
                    uint32_t hp = (uint32_t)__half_as_ushort(h0) |
                                  ((uint32_t)__half_as_ushort(h1) << 16);
                    *reinterpret_cast<uint32_t*>(&g_ah[(size_t)row * C_ + col]) = hp;
                }
                rsum += __shfl_xor_sync(0xffffffffu, rsum, 1);
                rsum += __shfl_xor_sync(0xffffffffu, rsum, 2);
                if ((lane & 3) == 0) atomicAdd(&g_rowsum[row], rsum);
            }
        }
    } else {
        #pragma unroll
        for (int mt = 0; mt < 4; mt++) {
            #pragma unroll
            for (int h = 0; h < 2; h++) {
                const int row = by * 128 + warp_m * 64 + mt * 16 + h * 8 + lr;
                const float inv = 1.0f / g_rowsum[row];
                #pragma unroll
                for (int nt = 0; nt < 4; nt++) {
                    const int col = bx * 128 + warp_n * 32 + nt * 8 + lc;
                    if (col < K_) {
                        float2 bb = *reinterpret_cast<const float2*>(&bias[col]);
                        float2 o;
                        o.x = acc[mt][nt][h * 2 + 0] * inv + bb.x;
                        o.y = acc[mt][nt][h * 2 + 1] * inv + bb.y;
                        *reinterpret_cast<float2*>(&out[(size_t)row * K_ + col]) = o;
                    }
                }
            }
        }
    }
}

// ---------------------------------------------------------------------------
extern "C" void kernel_launch(void* const* d_in, const int* in_sizes, int n_in,
                              void* d_out, int out_size) {
    const float* x       = (const float*)d_in[0];
    const float* centers = (const float*)d_in[1];
    const float* beta    = (const float*)d_in[2];
    const float* W       = (const float*)d_in[3];
    const float* bias    = (const float*)d_in[4];
    float* out = (float*)d_out;

    __half *xh, *chh, *chl, *whh, *whl, *ah;
    cudaGetSymbolAddress((void**)&xh,  g_xh);
    cudaGetSymbolAddress((void**)&chh, g_chh);
    cudaGetSymbolAddress((void**)&chl, g_chl);
    cudaGetSymbolAddress((void**)&whh, g_whh);
    cudaGetSymbolAddress((void**)&whl, g_whl);
    cudaGetSymbolAddress((void**)&ah,  g_ah);

    cudaFuncSetAttribute(gemm_f16_kernel<D_, 0>,
                         cudaFuncAttributeMaxDynamicSharedMemorySize, S_SMEM);
    cudaFuncSetAttribute(gemm_f16_kernel<C_, 1>,
                         cudaFuncAttributeMaxDynamicSharedMemorySize, S_SMEM);

    splitx_kernel<<<B_, 256>>>(x, xh);
    splitc_kernel<<<C_, 256>>>(centers, chh, chl);
    c2mean_kernel<<<1, 1024>>>();
    {
        int n4 = KPAD_ * C_ / 4;
        splitW_kernel<<<(n4 + 255) / 256, 256>>>(W);
    }

    dim3 g1(C_ / 128, B_ / 128);            // (32, 64)
    gemm_f16_kernel<D_, 0><<<g1, 256, S_SMEM>>>(xh, chh, chl, beta, bias, out);

    dim3 g2(KPAD_ / 128, B_ / 128);         // (8, 64)
    gemm_f16_kernel<C_, 1><<<g2, 256, S_SMEM>>>(ah, whh, whl, beta, bias, out);
}

// round 9
// speedup vs baseline: 4.3793x; 1.0047x over previous
#include <cuda_runtime.h>
#include <cuda_fp16.h>
#include <stdint.h>
#include <math.h>

#define B_ 8192
#define D_ 2048
#define C_ 4096
#define K_ 1000
#define KPAD_ 1024

// smem geometry: 128 rows x (64B data + 16B pad); 2 parts, 4 stages
#define ROWB 80
#define S_PART 10240               // 128 * 80
#define S_STAGE (2 * S_PART)       // 20480
#define NSTAGE 4
#define S_SMEM (NSTAGE * S_STAGE)  // 81920

// ---------------------------------------------------------------------------
// Device scratch
// ---------------------------------------------------------------------------
__device__ __align__(128) __half g_xh[(size_t)B_ * D_];
__device__ __align__(128) __half g_ch[(size_t)C_ * D_];
__device__ __align__(128) __half g_wh[(size_t)KPAD_ * C_];
__device__ __align__(128) __half g_ah[(size_t)B_ * C_];
__device__ float g_x2[B_], g_c2[C_], g_rowsum[B_];
__device__ float g_c2mean;

// ---------------------------------------------------------------------------
// PTX helpers
// ---------------------------------------------------------------------------
__device__ __forceinline__ uint32_t smem_u32(const void* p) {
    uint32_t a;
    asm("{ .reg .u64 t; cvta.to.shared.u64 t, %1; cvt.u32.u64 %0, t; }"
        : "=r"(a) : "l"(p));
    return a;
}

__device__ __forceinline__ void ldsm_x4(uint32_t& r0, uint32_t& r1, uint32_t& r2,
                                        uint32_t& r3, uint32_t addr) {
    asm volatile("ldmatrix.sync.aligned.m8n8.x4.shared.b16 {%0,%1,%2,%3}, [%4];"
                 : "=r"(r0), "=r"(r1), "=r"(r2), "=r"(r3) : "r"(addr));
}

__device__ __forceinline__ void mma_f16(float c[4], const uint32_t a[4],
                                        const uint32_t b[2]) {
    asm volatile(
        "mma.sync.aligned.m16n8k16.row.col.f32.f16.f16.f32 "
        "{%0,%1,%2,%3}, {%4,%5,%6,%7}, {%8,%9}, {%0,%1,%2,%3};"
        : "+f"(c[0]), "+f"(c[1]), "+f"(c[2]), "+f"(c[3])
        : "r"(a[0]), "r"(a[1]), "r"(a[2]), "r"(a[3]), "r"(b[0]), "r"(b[1]));
}

__device__ __forceinline__ void cp16(uint32_t dst, const void* src) {
    asm volatile("cp.async.cg.shared.global [%0], [%1], 16;"
                 :: "r"(dst), "l"(src) : "memory");
}
#define CP_COMMIT() asm volatile("cp.async.commit_group;" ::: "memory")
template <int N>
__device__ __forceinline__ void cp_wait() {
    asm volatile("cp.async.wait_group %0;" :: "n"(N) : "memory");
}

// ---------------------------------------------------------------------------
// Prologue kernels
// ---------------------------------------------------------------------------
__global__ void splitx_kernel(const float* __restrict__ x, __half* __restrict__ xh) {
    const int row = blockIdx.x;
    const float4* p = reinterpret_cast<const float4*>(x + (size_t)row * D_);
    float s = 0.f;
    for (int i = threadIdx.x; i < D_ / 4; i += blockDim.x) {
        float4 v = p[i];
        s += v.x * v.x + v.y * v.y + v.z * v.z + v.w * v.w;
        __half h[4] = {__float2half(v.x), __float2half(v.y),
                       __float2half(v.z), __float2half(v.w)};
        *reinterpret_cast<uint2*>(xh + (size_t)row * D_ + i * 4) =
            *reinterpret_cast<uint2*>(h);
    }
    #pragma unroll
    for (int o = 16; o; o >>= 1) s += __shfl_xor_sync(0xffffffffu, s, o);
    __shared__ float ws[8];
    if ((threadIdx.x & 31) == 0) ws[threadIdx.x >> 5] = s;
    __syncthreads();
    if (threadIdx.x == 0) {
        float t = 0.f;
        #pragma unroll
        for (int i = 0; i < 8; i++) t += ws[i];
        g_x2[row] = t;
        g_rowsum[row] = 0.f;
    }
}

__global__ void splitc_kernel(const float* __restrict__ cen, __half* __restrict__ ch) {
    const int row = blockIdx.x;
    const float4* p = reinterpret_cast<const float4*>(cen + (size_t)row * D_);
    float s = 0.f;
    for (int i = threadIdx.x; i < D_ / 4; i += blockDim.x) {
        float4 v = p[i];
        s += v.x * v.x + v.y * v.y + v.z * v.z + v.w * v.w;
        __half h[4] = {__float2half(v.x), __float2half(v.y),
                       __float2half(v.z), __float2half(v.w)};
        *reinterpret_cast<uint2*>(ch + (size_t)row * D_ + i * 4) =
            *reinterpret_cast<uint2*>(h);
    }
    #pragma unroll
    for (int o = 16; o; o >>= 1) s += __shfl_xor_sync(0xffffffffu, s, o);
    __shared__ float ws[8];
    if ((threadIdx.x & 31) == 0) ws[threadIdx.x >> 5] = s;
    __syncthreads();
    if (threadIdx.x == 0) {
        float t = 0.f;
        #pragma unroll
        for (int i = 0; i < 8; i++) t += ws[i];
        g_c2[row] = t;
    }
}

__global__ void c2mean_kernel() {
    float s = 0.f;
    for (int i = threadIdx.x; i < C_; i += 1024) s += g_c2[i];
    #pragma unroll
    for (int o = 16; o; o >>= 1) s += __shfl_xor_sync(0xffffffffu, s, o);
    __shared__ float ws[32];
    if ((threadIdx.x & 31) == 0) ws[threadIdx.x >> 5] = s;
    __syncthreads();
    if (threadIdx.x == 0) {
        float t = 0.f;
        #pragma unroll
        for (int i = 0; i < 32; i++) t += ws[i];
        g_c2mean = t * (1.f / C_);
    }
}

__global__ void splitW_kernel(const float* __restrict__ W) {
    int i = blockIdx.x * blockDim.x + threadIdx.x;
    if (i >= KPAD_ * C_ / 4) return;
    int r = i >> 10;
    int c0 = (i & 1023) * 4;
    float f[4] = {0.f, 0.f, 0.f, 0.f};
    if (r < K_) {
        float4 v = *reinterpret_cast<const float4*>(W + (size_t)r * C_ + c0);
        f[0] = v.x; f[1] = v.y; f[2] = v.z; f[3] = v.w;
    }
    __half h[4] = {__float2half(f[0]), __float2half(f[1]),
                   __float2half(f[2]), __float2half(f[3])};
    *reinterpret_cast<uint2*>(g_wh + (size_t)r * C_ + c0) = *reinterpret_cast<uint2*>(h);
}

// ---------------------------------------------------------------------------
// fp16 1-pass GEMM (A x B), 128x128 CTA, 8 warps (64x32 warp tiles),
// K-chunk 32, 4-stage cp.async pipeline (always-commit tail), one
// __syncthreads per chunk, 2 CTAs/SM.
// MODE 0 (GEMM1): A=xh, B=ch. Epilogue: shifted RBF -> fp16 a' + rowsum.
// MODE 1 (GEMM2): A=a', B=wh. Epilogue: out = acc/rowsum + bias.
// ---------------------------------------------------------------------------
template <int KDIM, int MODE>
__global__ __launch_bounds__(256, 2) void gemm_f16_kernel(
    const __half* __restrict__ Ah, const __half* __restrict__ Bh,
    const float* __restrict__ beta, const float* __restrict__ bias,
    float* __restrict__ out)
{
    constexpr int NCH = KDIM / 32;
    extern __shared__ char smem[];
    const uint32_t sb = smem_u32(smem);
    const int tid = threadIdx.x;
    const int w = tid >> 5, lane = tid & 31;
    const int warp_m = w >> 2, warp_n = w & 3;
    const int bx = blockIdx.x, by = blockIdx.y;

    // loader: 2 parts; each thread covers rows (tid>>2), (tid>>2)+64, granule tid&3
    const int lrow = tid >> 2, lg = tid & 3;
    const __half* srcP0 = Ah + (size_t)(by * 128 + lrow) * KDIM + lg * 8;
    const __half* srcP1 = Bh + (size_t)(bx * 128 + lrow) * KDIM + lg * 8;
    const uint32_t d0 = 0 * S_PART + lrow * ROWB + lg * 16;
    const uint32_t d1 = 1 * S_PART + lrow * ROWB + lg * 16;

    float acc[4][4][4];
    #pragma unroll
    for (int mt = 0; mt < 4; mt++)
        #pragma unroll
        for (int nt = 0; nt < 4; nt++)
            #pragma unroll
            for (int q = 0; q < 4; q++) acc[mt][nt][q] = 0.f;

#define S_ISSUE(stage, c) do {                                               \
        const uint32_t stb_ = sb + (stage) * S_STAGE;                        \
        const int co_ = (c) * 32;                                            \
        cp16(stb_ + d0, srcP0 + co_);                                        \
        cp16(stb_ + d0 + 64 * ROWB, srcP0 + (size_t)64 * KDIM + co_);        \
        cp16(stb_ + d1, srcP1 + co_);                                        \
        cp16(stb_ + d1 + 64 * ROWB, srcP1 + (size_t)64 * KDIM + co_);        \
        CP_COMMIT();                                                         \
    } while (0)

    S_ISSUE(0, 0);
    S_ISSUE(1, 1);
    S_ISSUE(2, 2);

    const uint32_t aoff = (uint32_t)(warp_m * 64 + (lane & 15)) * ROWB +
                          (uint32_t)((lane >> 4) << 3) * 2;
    const uint32_t boff = (uint32_t)(warp_n * 32 + (lane & 7) + ((lane >> 4) << 3)) * ROWB +
                          (uint32_t)(lane & 8) * 2;

    int st = 0, ld = 3;
    #pragma unroll 1
    for (int c = 0; c < NCH; c++) {
        cp_wait<2>();           // chunk c resident (3 groups in flight max)
        __syncthreads();
        if (c + 3 < NCH) {
            S_ISSUE(ld, c + 3);
        } else {
            CP_COMMIT();        // empty group keeps the wait<2> arithmetic exact
        }

        const uint32_t bufb = sb + st * S_STAGE;
        #pragma unroll
        for (int ks = 0; ks < 2; ks++) {
            const uint32_t kso = ks * 32;
            uint32_t AH[4][4], BB[4][2];
            #pragma unroll
            for (int mt = 0; mt < 4; mt++)
                ldsm_x4(AH[mt][0], AH[mt][1], AH[mt][2], AH[mt][3],
                        bufb + aoff + kso + mt * 16 * ROWB);
            #pragma unroll
            for (int np = 0; np < 2; np++) {
                uint32_t r0, r1, r2, r3;
                ldsm_x4(r0, r1, r2, r3,
                        bufb + S_PART + boff + kso + np * 16 * ROWB);
                BB[np * 2][0] = r0; BB[np * 2][1] = r1;
                BB[np * 2 + 1][0] = r2; BB[np * 2 + 1][1] = r3;
            }
            #pragma unroll
            for (int mt = 0; mt < 4; mt++)
                #pragma unroll
                for (int nt = 0; nt < 4; nt++)
                    mma_f16(acc[mt][nt], AH[mt], BB[nt]);
        }
        st = (st + 1 == NSTAGE) ? 0 : st + 1;
        ld = (ld + 1 == NSTAGE) ? 0 : ld + 1;
    }
#undef S_ISSUE

    // ------------------------------ epilogue -------------------------------
    const int lr = lane >> 2;
    const int lc = (lane & 3) * 2;

    if (MODE == 0) {
        const float c2m = g_c2mean;
        #pragma unroll
        for (int mt = 0; mt < 4; mt++) {
            #pragma unroll
            for (int h = 0; h < 2; h++) {
                const int row = by * 128 + warp_m * 64 + mt * 16 + h * 8 + lr;
                const float x2v = g_x2[row];
                const float shift = sqrtf(x2v + c2m) - 4.0f;
                float rsum = 0.f;
                #pragma unroll
                for (int nt = 0; nt < 4; nt++) {
                    const int col = bx * 128 + warp_n * 32 + nt * 8 + lc;
                    const float dd0 = acc[mt][nt][h * 2 + 0];
                    const float dd1 = acc[mt][nt][h * 2 + 1];
                    float sq0 = x2v + g_c2[col]     - 2.f * dd0;
                    float sq1 = x2v + g_c2[col + 1] - 2.f * dd1;
                    float e0 = fminf(shift - beta[col]     * sqrtf(fmaxf(sq0, 0.f)), 10.f);
                    float e1 = fminf(shift - beta[col + 1] * sqrtf(fmaxf(sq1, 0.f)), 10.f);
                    float v0 = __expf(e0);
                    float v1 = __expf(e1);
                    rsum += v0 + v1;
                    __half h0 = __float2half(v0);
                    __half h1 = __float2half(v1);
                    uint32_t hp = (uint32_t)__half_as_ushort(h0) |
                                  ((uint32_t)__half_as_ushort(h1) << 16);
                    *reinterpret_cast<uint32_t*>(&g_ah[(size_t)row * C_ + col]) = hp;
                }
                rsum += __shfl_xor_sync(0xffffffffu, rsum, 1);
                rsum += __shfl_xor_sync(0xffffffffu, rsum, 2);
                if ((lane & 3) == 0) atomicAdd(&g_rowsum[row], rsum);
            }
        }
    } else {
        #pragma unroll
        for (int mt = 0; mt < 4; mt++) {
            #pragma unroll
            for (int h = 0; h < 2; h++) {
                const int row = by * 128 + warp_m * 64 + mt * 16 + h * 8 + lr;
                const float inv = 1.0f / g_rowsum[row];
                #pragma unroll
                for (int nt = 0; nt < 4; nt++) {
                    const int col = bx * 128 + warp_n * 32 + nt * 8 + lc;
                    if (col < K_) {
                        float2 bb = *reinterpret_cast<const float2*>(&bias[col]);
                        float2 o;
                        o.x = acc[mt][nt][h * 2 + 0] * inv + bb.x;
                        o.y = acc[mt][nt][h * 2 + 1] * inv + bb.y;
                        *reinterpret_cast<float2*>(&out[(size_t)row * K_ + col]) = o;
                    }
                }
            }
        }
    }
}

// ---------------------------------------------------------------------------
extern "C" void kernel_launch(void* const* d_in, const int* in_sizes, int n_in,
                              void* d_out, int out_size) {
    const float* x       = (const float*)d_in[0];
    const float* centers = (const float*)d_in[1];
    const float* beta    = (const float*)d_in[2];
    const float* W       = (const float*)d_in[3];
    const float* bias    = (const float*)d_in[4];
    float* out = (float*)d_out;

    __half *xh, *ch, *wh, *ah;
    cudaGetSymbolAddress((void**)&xh, g_xh);
    cudaGetSymbolAddress((void**)&ch, g_ch);
    cudaGetSymbolAddress((void**)&wh, g_wh);
    cudaGetSymbolAddress((void**)&ah, g_ah);

    cudaFuncSetAttribute(gemm_f16_kernel<D_, 0>,
                         cudaFuncAttributeMaxDynamicSharedMemorySize, S_SMEM);
    cudaFuncSetAttribute(gemm_f16_kernel<C_, 1>,
                         cudaFuncAttributeMaxDynamicSharedMemorySize, S_SMEM);

    splitx_kernel<<<B_, 256>>>(x, xh);
    splitc_kernel<<<C_, 256>>>(centers, ch);
    c2mean_kernel<<<1, 1024>>>();
    {
        int n4 = KPAD_ * C_ / 4;
        splitW_kernel<<<(n4 + 255) / 256, 256>>>(W);
    }

    dim3 g1(C_ / 128, B_ / 128);            // (32, 64)
    gemm_f16_kernel<D_, 0><<<g1, 256, S_SMEM>>>(xh, ch, beta, bias, out);

    dim3 g2(KPAD_ / 128, B_ / 128);         // (8, 64)
    gemm_f16_kernel<C_, 1><<<g2, 256, S_SMEM>>>(ah, wh, beta, bias, out);
}

// round 10
// speedup vs baseline: 4.7830x; 1.0922x over previous
#include <cuda_runtime.h>
#include <cuda_fp16.h>
#include <stdint.h>
#include <math.h>

#define B_ 8192
#define D_ 2048
#define C_ 4096
#define K_ 1000
#define KPAD_ 1024

// smem geometry: K-chunk 64 halfs = 128B data + 16B pad per row
#define ROWB 144
#define A_ROWS 256
#define B_ROWS 128
#define PART_A (A_ROWS * ROWB)      // 36864
#define PART_B (B_ROWS * ROWB)      // 18432
#define S_STAGE (PART_A + PART_B)   // 55296
#define NSTAGE 3
#define S_SMEM (NSTAGE * S_STAGE)   // 165888

// ---------------------------------------------------------------------------
// Device scratch
// ---------------------------------------------------------------------------
__device__ __align__(128) __half g_xh[(size_t)B_ * D_];
__device__ __align__(128) __half g_ch[(size_t)C_ * D_];
__device__ __align__(128) __half g_wh[(size_t)KPAD_ * C_];
__device__ __align__(128) __half g_ah[(size_t)B_ * C_];
__device__ float g_x2[B_], g_c2[C_], g_rowsum[B_];
__device__ float g_c2mean;

// ---------------------------------------------------------------------------
// PTX helpers
// ---------------------------------------------------------------------------
__device__ __forceinline__ uint32_t smem_u32(const void* p) {
    uint32_t a;
    asm("{ .reg .u64 t; cvta.to.shared.u64 t, %1; cvt.u32.u64 %0, t; }"
        : "=r"(a) : "l"(p));
    return a;
}

__device__ __forceinline__ void ldsm_x4(uint32_t& r0, uint32_t& r1, uint32_t& r2,
                                        uint32_t& r3, uint32_t addr) {
    asm volatile("ldmatrix.sync.aligned.m8n8.x4.shared.b16 {%0,%1,%2,%3}, [%4];"
                 : "=r"(r0), "=r"(r1), "=r"(r2), "=r"(r3) : "r"(addr));
}

__device__ __forceinline__ void mma_f16(float c[4], const uint32_t a[4],
                                        const uint32_t b[2]) {
    asm volatile(
        "mma.sync.aligned.m16n8k16.row.col.f32.f16.f16.f32 "
        "{%0,%1,%2,%3}, {%4,%5,%6,%7}, {%8,%9}, {%0,%1,%2,%3};"
        : "+f"(c[0]), "+f"(c[1]), "+f"(c[2]), "+f"(c[3])
        : "r"(a[0]), "r"(a[1]), "r"(a[2]), "r"(a[3]), "r"(b[0]), "r"(b[1]));
}

__device__ __forceinline__ void cp16(uint32_t dst, const void* src) {
    asm volatile("cp.async.cg.shared.global [%0], [%1], 16;"
                 :: "r"(dst), "l"(src) : "memory");
}
#define CP_COMMIT() asm volatile("cp.async.commit_group;" ::: "memory")
template <int N>
__device__ __forceinline__ void cp_wait() {
    asm volatile("cp.async.wait_group %0;" :: "n"(N) : "memory");
}

// ---------------------------------------------------------------------------
// Prologue kernels (unchanged from R9)
// ---------------------------------------------------------------------------
__global__ void splitx_kernel(const float* __restrict__ x, __half* __restrict__ xh) {
    const int row = blockIdx.x;
    const float4* p = reinterpret_cast<const float4*>(x + (size_t)row * D_);
    float s = 0.f;
    for (int i = threadIdx.x; i < D_ / 4; i += blockDim.x) {
        float4 v = p[i];
        s += v.x * v.x + v.y * v.y + v.z * v.z + v.w * v.w;
        __half h[4] = {__float2half(v.x), __float2half(v.y),
                       __float2half(v.z), __float2half(v.w)};
        *reinterpret_cast<uint2*>(xh + (size_t)row * D_ + i * 4) =
            *reinterpret_cast<uint2*>(h);
    }
    #pragma unroll
    for (int o = 16; o; o >>= 1) s += __shfl_xor_sync(0xffffffffu, s, o);
    __shared__ float ws[8];
    if ((threadIdx.x & 31) == 0) ws[threadIdx.x >> 5] = s;
    __syncthreads();
    if (threadIdx.x == 0) {
        float t = 0.f;
        #pragma unroll
        for (int i = 0; i < 8; i++) t += ws[i];
        g_x2[row] = t;
        g_rowsum[row] = 0.f;
    }
}

__global__ void splitc_kernel(const float* __restrict__ cen, __half* __restrict__ ch) {
    const int row = blockIdx.x;
    const float4* p = reinterpret_cast<const float4*>(cen + (size_t)row * D_);
    float s = 0.f;
    for (int i = threadIdx.x; i < D_ / 4; i += blockDim.x) {
        float4 v = p[i];
        s += v.x * v.x + v.y * v.y + v.z * v.z + v.w * v.w;
        __half h[4] = {__float2half(v.x), __float2half(v.y),
                       __float2half(v.z), __float2half(v.w)};
        *reinterpret_cast<uint2*>(ch + (size_t)row * D_ + i * 4) =
            *reinterpret_cast<uint2*>(h);
    }
    #pragma unroll
    for (int o = 16; o; o >>= 1) s += __shfl_xor_sync(0xffffffffu, s, o);
    __shared__ float ws[8];
    if ((threadIdx.x & 31) == 0) ws[threadIdx.x >> 5] = s;
    __syncthreads();
    if (threadIdx.x == 0) {
        float t = 0.f;
        #pragma unroll
        for (int i = 0; i < 8; i++) t += ws[i];
        g_c2[row] = t;
    }
}

__global__ void c2mean_kernel() {
    float s = 0.f;
    for (int i = threadIdx.x; i < C_; i += 1024) s += g_c2[i];
    #pragma unroll
    for (int o = 16; o; o >>= 1) s += __shfl_xor_sync(0xffffffffu, s, o);
    __shared__ float ws[32];
    if ((threadIdx.x & 31) == 0) ws[threadIdx.x >> 5] = s;
    __syncthreads();
    if (threadIdx.x == 0) {
        float t = 0.f;
        #pragma unroll
        for (int i = 0; i < 32; i++) t += ws[i];
        g_c2mean = t * (1.f / C_);
    }
}

__global__ void splitW_kernel(const float* __restrict__ W) {
    int i = blockIdx.x * blockDim.x + threadIdx.x;
    if (i >= KPAD_ * C_ / 4) return;
    int r = i >> 10;
    int c0 = (i & 1023) * 4;
    float f[4] = {0.f, 0.f, 0.f, 0.f};
    if (r < K_) {
        float4 v = *reinterpret_cast<const float4*>(W + (size_t)r * C_ + c0);
        f[0] = v.x; f[1] = v.y; f[2] = v.z; f[3] = v.w;
    }
    __half h[4] = {__float2half(f[0]), __float2half(f[1]),
                   __float2half(f[2]), __float2half(f[3])};
    *reinterpret_cast<uint2*>(g_wh + (size_t)r * C_ + c0) = *reinterpret_cast<uint2*>(h);
}

// ---------------------------------------------------------------------------
// fp16 1-pass GEMM: CTA tile 256x128, 8 warps (4x2, warp tile 64x64),
// K-chunk 64, 3-stage cp.async pipeline, one __syncthreads per chunk,
// 1 CTA/SM (255 regs: acc=128 fp32 per thread).
// MODE 0 (GEMM1): A=xh, B=ch. Epilogue: shifted RBF -> fp16 a' + rowsum.
// MODE 1 (GEMM2): A=a', B=wh. Epilogue: out = acc/rowsum + bias.
// ---------------------------------------------------------------------------
template <int KDIM, int MODE>
__global__ __launch_bounds__(256, 1) void gemm_f16_kernel(
    const __half* __restrict__ Ah, const __half* __restrict__ Bh,
    const float* __restrict__ beta, const float* __restrict__ bias,
    float* __restrict__ out)
{
    constexpr int NCH = KDIM / 64;
    extern __shared__ char smem[];
    const uint32_t sb = smem_u32(smem);
    const int tid = threadIdx.x;
    const int w = tid >> 5, lane = tid & 31;
    const int warp_m = w >> 1, warp_n = w & 1;   // 4x2 grid of 64x64 tiles
    const int bx = blockIdx.x, by = blockIdx.y;

    // ---- loader mapping ----
    // A: thread t loads its row (256 rows), 8 granules of 16B.
    // B: thread t loads row t&127, granules (t>>7)*4 .. +3.
    const __half* srcA = Ah + (size_t)(by * 256 + tid) * KDIM;
    const int brow = tid & 127;
    const int bgb = (tid >> 7) * 4;
    const __half* srcB = Bh + (size_t)(bx * 128 + brow) * KDIM + bgb * 8;
    const uint32_t dA = tid * ROWB;
    const uint32_t dB = PART_A + brow * ROWB + bgb * 16;

    float acc[4][8][4];
    #pragma unroll
    for (int mt = 0; mt < 4; mt++)
        #pragma unroll
        for (int nt = 0; nt < 8; nt++)
            #pragma unroll
            for (int q = 0; q < 4; q++) acc[mt][nt][q] = 0.f;

#define S_ISSUE(stage, c) do {                                               \
        const uint32_t stb_ = sb + (stage) * S_STAGE;                        \
        const int co_ = (c) * 64;                                            \
        _Pragma("unroll")                                                    \
        for (int g_ = 0; g_ < 8; g_++)                                       \
            cp16(stb_ + dA + g_ * 16, srcA + co_ + g_ * 8);                  \
        _Pragma("unroll")                                                    \
        for (int g_ = 0; g_ < 4; g_++)                                       \
            cp16(stb_ + dB + g_ * 16, srcB + co_ + g_ * 8);                  \
        CP_COMMIT();                                                         \
    } while (0)

    S_ISSUE(0, 0);
    S_ISSUE(1, 1);

    const uint32_t aoff = (uint32_t)(warp_m * 64 + (lane & 15)) * ROWB +
                          (uint32_t)((lane >> 4) << 3) * 2;
    const uint32_t boff = PART_A +
                          (uint32_t)(warp_n * 64 + (lane & 7) + ((lane >> 4) << 3)) * ROWB +
                          (uint32_t)(lane & 8) * 2;

    int st = 0, ld = 2;
    #pragma unroll 1
    for (int c = 0; c < NCH; c++) {
        cp_wait<1>();            // chunk c resident
        __syncthreads();
        if (c + 2 < NCH) {
            S_ISSUE(ld, c + 2);
        } else {
            CP_COMMIT();         // empty group keeps wait<1> arithmetic exact
        }

        const uint32_t bufb = sb + st * S_STAGE;
        #pragma unroll
        for (int ks = 0; ks < 4; ks++) {
            const uint32_t kso = ks * 32;
            uint32_t AH[4][4], BB[8][2];
            #pragma unroll
            for (int mt = 0; mt < 4; mt++)
                ldsm_x4(AH[mt][0], AH[mt][1], AH[mt][2], AH[mt][3],
                        bufb + aoff + kso + mt * 16 * ROWB);
            #pragma unroll
            for (int np = 0; np < 4; np++) {
                uint32_t r0, r1, r2, r3;
                ldsm_x4(r0, r1, r2, r3,
                        bufb + boff + kso + np * 16 * ROWB);
                BB[np * 2][0] = r0; BB[np * 2][1] = r1;
                BB[np * 2 + 1][0] = r2; BB[np * 2 + 1][1] = r3;
            }
            #pragma unroll
            for (int mt = 0; mt < 4; mt++)
                #pragma unroll
                for (int nt = 0; nt < 8; nt++)
                    mma_f16(acc[mt][nt], AH[mt], BB[nt]);
        }
        st = (st + 1 == NSTAGE) ? 0 : st + 1;
        ld = (ld + 1 == NSTAGE) ? 0 : ld + 1;
    }
#undef S_ISSUE

    // ------------------------------ epilogue -------------------------------
    const int lr = lane >> 2;
    const int lc = (lane & 3) * 2;

    if (MODE == 0) {
        const float c2m = g_c2mean;
        #pragma unroll
        for (int mt = 0; mt < 4; mt++) {
            #pragma unroll
            for (int h = 0; h < 2; h++) {
                const int row = by * 256 + warp_m * 64 + mt * 16 + h * 8 + lr;
                const float x2v = g_x2[row];
                const float shift = sqrtf(x2v + c2m) - 4.0f;
                float rsum = 0.f;
                #pragma unroll
                for (int nt = 0; nt < 8; nt++) {
                    const int col = bx * 128 + warp_n * 64 + nt * 8 + lc;
                    const float dd0 = acc[mt][nt][h * 2 + 0];
                    const float dd1 = acc[mt][nt][h * 2 + 1];
                    float sq0 = x2v + g_c2[col]     - 2.f * dd0;
                    float sq1 = x2v + g_c2[col + 1] - 2.f * dd1;
                    float e0 = fminf(shift - beta[col]     * sqrtf(fmaxf(sq0, 0.f)), 10.f);
                    float e1 = fminf(shift - beta[col + 1] * sqrtf(fmaxf(sq1, 0.f)), 10.f);
                    float v0 = __expf(e0);
                    float v1 = __expf(e1);
                    rsum += v0 + v1;
                    __half h0 = __float2half(v0);
                    __half h1 = __float2half(v1);
                    uint32_t hp = (uint32_t)__half_as_ushort(h0) |
                                  ((uint32_t)__half_as_ushort(h1) << 16);
                    *reinterpret_cast<uint32_t*>(&g_ah[(size_t)row * C_ + col]) = hp;
                }
                rsum += __shfl_xor_sync(0xffffffffu, rsum, 1);
                rsum += __shfl_xor_sync(0xffffffffu, rsum, 2);
                if ((lane & 3) == 0) atomicAdd(&g_rowsum[row], rsum);
            }
        }
    } else {
        #pragma unroll
        for (int mt = 0; mt < 4; mt++) {
            #pragma unroll
            for (int h = 0; h < 2; h++) {
                const int row = by * 256 + warp_m * 64 + mt * 16 + h * 8 + lr;
                const float inv = 1.0f / g_rowsum[row];
                #pragma unroll
                for (int nt = 0; nt < 8; nt++) {
                    const int col = bx * 128 + warp_n * 64 + nt * 8 + lc;
                    if (col < K_) {
                        float2 bb = *reinterpret_cast<const float2*>(&bias[col]);
                        float2 o;
                        o.x = acc[mt][nt][h * 2 + 0] * inv + bb.x;
                        o.y = acc[mt][nt][h * 2 + 1] * inv + bb.y;
                        *reinterpret_cast<float2*>(&out[(size_t)row * K_ + col]) = o;
                    }
                }
            }
        }
    }
}

// ---------------------------------------------------------------------------
extern "C" void kernel_launch(void* const* d_in, const int* in_sizes, int n_in,
                              void* d_out, int out_size) {
    const float* x       = (const float*)d_in[0];
    const float* centers = (const float*)d_in[1];
    const float* beta    = (const float*)d_in[2];
    const float* W       = (const float*)d_in[3];
    const float* bias    = (const float*)d_in[4];
    float* out = (float*)d_out;

    __half *xh, *ch, *wh, *ah;
    cudaGetSymbolAddress((void**)&xh, g_xh);
    cudaGetSymbolAddress((void**)&ch, g_ch);
    cudaGetSymbolAddress((void**)&wh, g_wh);
    cudaGetSymbolAddress((void**)&ah, g_ah);

    cudaFuncSetAttribute(gemm_f16_kernel<D_, 0>,
                         cudaFuncAttributeMaxDynamicSharedMemorySize, S_SMEM);
    cudaFuncSetAttribute(gemm_f16_kernel<C_, 1>,
                         cudaFuncAttributeMaxDynamicSharedMemorySize, S_SMEM);

    splitx_kernel<<<B_, 256>>>(x, xh);
    splitc_kernel<<<C_, 256>>>(centers, ch);
    c2mean_kernel<<<1, 1024>>>();
    {
        int n4 = KPAD_ * C_ / 4;
        splitW_kernel<<<(n4 + 255) / 256, 256>>>(W);
    }

    dim3 g1(C_ / 128, B_ / 256);            // (32, 32)
    gemm_f16_kernel<D_, 0><<<g1, 256, S_SMEM>>>(xh, ch, beta, bias, out);

    dim3 g2(KPAD_ / 128, B_ / 256);         // (8, 32)
    gemm_f16_kernel<C_, 1><<<g2, 256, S_SMEM>>>(ah, wh, beta, bias, out);
}